// round 4
// baseline (speedup 1.0000x reference)
#include <cuda_runtime.h>

// QuantumRegression: 1024 x 14-qubit statevector sim, 3 layers (Rot per wire + CNOT ring),
// <Z_w> features, linear head.
//
// R4: NT=512 with strict register budget (<128/thread, no spills):
//  - all passes use 16-amp (or 4-amp) register tiles, ONE Mat4 live at a time
//  - gate matrices staged in spare SMEM, re-read via broadcast LDS per tile
//  - per layer: P1 bits 13..10 | P2 bits 9..6 | P2b bits 5,4 | P3 bits 3..0 (rotated float4)
//  - CNOT perm: register staging tmp[32] between layers; final perm folded into measurement
//  - layer-0 P1 fused with gmem load; layer-2 P3 fused with measurement

#define NW   14
#define DIM  16384
#define NT   512

typedef unsigned long long u64;

__device__ float4 g_mats[21][16];   // per wire-pair 4x4: {ur, ur, -ui, ui}

// ---------------- setup: build fused 4x4 gate matrices ----------------

struct cpx { float re, im; };
__device__ __forceinline__ cpx cmul(cpx a, cpx b){
    cpx r; r.re = a.re*b.re - a.im*b.im; r.im = a.re*b.im + a.im*b.re; return r;
}

__device__ void rotmat(const float* p, cpx U[2][2]){
    float cx = cosf(0.5f*p[0]), sx = sinf(0.5f*p[0]);
    float cy = cosf(0.5f*p[1]), sy = sinf(0.5f*p[1]);
    float cz = cosf(0.5f*p[2]), sz = sinf(0.5f*p[2]);
    cpx r00 = { cy*cx,  sy*sx};
    cpx r01 = {-sy*cx, -cy*sx};
    cpx r10 = { sy*cx, -cy*sx};
    cpx r11 = { cy*cx, -sy*sx};
    cpx e0 = {cz, -sz}, e1 = {cz, sz};
    U[0][0] = cmul(e0, r00); U[0][1] = cmul(e0, r01);
    U[1][0] = cmul(e1, r10); U[1][1] = cmul(e1, r11);
}

__global__ void setup_mats(const float* __restrict__ vp){
    int pid = threadIdx.x;
    if (pid >= 21) return;
    int l = pid / 7, k = pid % 7;
    cpx Ua[2][2], Ub[2][2];
    rotmat(vp + (l*NW + 2*k    )*3, Ua);
    rotmat(vp + (l*NW + 2*k + 1)*3, Ub);
    #pragma unroll
    for (int i = 0; i < 2; i++)
    #pragma unroll
    for (int j = 0; j < 2; j++)
    #pragma unroll
    for (int a = 0; a < 2; a++)
    #pragma unroll
    for (int c = 0; c < 2; c++){
        cpx m = cmul(Ua[i][a], Ub[j][c]);        // kron: wire 2k more significant
        g_mats[pid][(2*i + j)*4 + (2*a + c)] = make_float4(m.re, m.re, -m.im, m.im);
    }
}

// ---------------- packed f32x2 helpers ----------------

__device__ __forceinline__ u64 pk2(float lo, float hi){
    u64 r; asm("mov.b64 %0, {%1,%2};" : "=l"(r) : "f"(lo), "f"(hi)); return r;
}
__device__ __forceinline__ void upk2(u64 v, float& lo, float& hi){
    asm("mov.b64 {%0,%1}, %2;" : "=f"(lo), "=f"(hi) : "l"(v));
}
__device__ __forceinline__ u64 swp2(u64 v){
    u64 r;
    asm("{ .reg .b32 a,b; mov.b64 {a,b}, %1; mov.b64 %0, {b,a}; }" : "=l"(r) : "l"(v));
    return r;
}
__device__ __forceinline__ u64 f2(u64 a, u64 b, u64 c){
    u64 r; asm("fma.rn.f32x2 %0, %1, %2, %3;" : "=l"(r) : "l"(a), "l"(b), "l"(c)); return r;
}
__device__ __forceinline__ u64 m2(u64 a, u64 b){
    u64 r; asm("mul.rn.f32x2 %0, %1, %2;" : "=l"(r) : "l"(a), "l"(b)); return r;
}

struct Mat4 { u64 u[16], n[16]; };

// broadcast-load a pair matrix from smem
__device__ __forceinline__ void loadmatS(Mat4& M, const float4* smats, int pair){
    #pragma unroll
    for (int e = 0; e < 16; e++){
        float4 f = smats[pair*16 + e];
        M.u[e] = pk2(f.x, f.y);
        M.n[e] = pk2(f.z, f.w);
    }
}

// in-place 4x4 complex matvec over amp[i0..i3] (packed (re,im))
__device__ __forceinline__ void applyGroup(const Mat4& M, u64* amp,
                                           int i0, int i1, int i2, int i3){
    u64 v0 = amp[i0], v1 = amp[i1], v2 = amp[i2], v3 = amp[i3];
    u64 s0 = swp2(v0), s1 = swp2(v1), s2 = swp2(v2), s3 = swp2(v3);
    u64 o0, o1, o2, o3;
    {
        u64 a = m2(M.u[0], v0); a = f2(M.n[0], s0, a);
        a = f2(M.u[1], v1, a);  a = f2(M.n[1], s1, a);
        a = f2(M.u[2], v2, a);  a = f2(M.n[2], s2, a);
        a = f2(M.u[3], v3, a);  a = f2(M.n[3], s3, a);
        o0 = a;
    }
    {
        u64 a = m2(M.u[4], v0); a = f2(M.n[4], s0, a);
        a = f2(M.u[5], v1, a);  a = f2(M.n[5], s1, a);
        a = f2(M.u[6], v2, a);  a = f2(M.n[6], s2, a);
        a = f2(M.u[7], v3, a);  a = f2(M.n[7], s3, a);
        o1 = a;
    }
    {
        u64 a = m2(M.u[8], v0);  a = f2(M.n[8], s0, a);
        a = f2(M.u[9], v1, a);   a = f2(M.n[9], s1, a);
        a = f2(M.u[10], v2, a);  a = f2(M.n[10], s2, a);
        a = f2(M.u[11], v3, a);  a = f2(M.n[11], s3, a);
        o2 = a;
    }
    {
        u64 a = m2(M.u[12], v0); a = f2(M.n[12], s0, a);
        a = f2(M.u[13], v1, a);  a = f2(M.n[13], s1, a);
        a = f2(M.u[14], v2, a);  a = f2(M.n[14], s2, a);
        a = f2(M.u[15], v3, a);  a = f2(M.n[15], s3, a);
        o3 = a;
    }
    amp[i0] = o0; amp[i1] = o1; amp[i2] = o2; amp[i3] = o3;
}

// apply both pair matrices of a 16-amp tile: pa on f-bits 3,2 ; pb on f-bits 1,0
__device__ __forceinline__ void applyTile(u64* amp, const float4* smats, int pa, int pb){
    Mat4 M;
    loadmatS(M, smats, pa);
    #pragma unroll
    for (int q = 0; q < 4; q++)
        applyGroup(M, amp, q, 4+q, 8+q, 12+q);
    loadmatS(M, smats, pb);
    #pragma unroll
    for (int q = 0; q < 4; q++)
        applyGroup(M, amp, q<<2, (q<<2)|1, (q<<2)|2, (q<<2)|3);
}

// ---------------- CNOT-ring permutation (GF2 linear) ----------------
__device__ __forceinline__ int pfwd(int i){
    int y = i;
    y ^= y >> 1; y ^= y >> 2; y ^= y >> 4; y ^= y >> 8;
    return (y & 0x1FFF) ^ ((((y ^ (i >> 13)) & 1) << 13));
}
__device__ __forceinline__ int pinv(int o){
    int t = o ^ (o >> 1);
    return (t & 0x1FFF) ^ (o & 0x2000) ^ ((o & 1) ? 0x3000 : 0);
}

// ---------------- passes ----------------

// P1: pairs (l*7+0, l*7+1) @ bits 13..10
__device__ __forceinline__ void passP1(float2* psi, const float4* smats, int l, int t){
    #pragma unroll 1
    for (int j = 0; j < DIM/16/NT; j++){
        int gid = t + NT*j;
        u64 amp[16];
        #pragma unroll
        for (int f = 0; f < 16; f++){
            float2 a = psi[(f << 10) | gid];
            amp[f] = pk2(a.x, a.y);
        }
        applyTile(amp, smats, l*7 + 0, l*7 + 1);
        #pragma unroll
        for (int f = 0; f < 16; f++){
            float x, y; upk2(amp[f], x, y);
            psi[(f << 10) | gid] = make_float2(x, y);
        }
    }
}

// P2: pairs (l*7+2, l*7+3) @ bits 9..6
__device__ __forceinline__ void passP2(float2* psi, const float4* smats, int l, int t){
    #pragma unroll 1
    for (int j = 0; j < DIM/16/NT; j++){
        int g = t + NT*j;
        int base = ((g >> 6) << 10) | (g & 63);
        u64 amp[16];
        #pragma unroll
        for (int f = 0; f < 16; f++){
            float2 a = psi[base + (f << 6)];
            amp[f] = pk2(a.x, a.y);
        }
        applyTile(amp, smats, l*7 + 2, l*7 + 3);
        #pragma unroll
        for (int f = 0; f < 16; f++){
            float x, y; upk2(amp[f], x, y);
            psi[base + (f << 6)] = make_float2(x, y);
        }
    }
}

// P2b: pair (l*7+4) @ bits 5,4 : 4-amp groups, matrix kept in regs across groups
__device__ __forceinline__ void passP2b(float2* psi, const float4* smats, int l, int t){
    Mat4 M; loadmatS(M, smats, l*7 + 4);
    #pragma unroll 1
    for (int j = 0; j < DIM/4/NT; j++){
        int g = t + NT*j;
        int base = ((g >> 4) << 6) | (g & 15);
        u64 a4[4];
        #pragma unroll
        for (int f = 0; f < 4; f++){
            float2 a = psi[base + (f << 4)];
            a4[f] = pk2(a.x, a.y);
        }
        applyGroup(M, a4, 0, 1, 2, 3);
        #pragma unroll
        for (int f = 0; f < 4; f++){
            float x, y; upk2(a4[f], x, y);
            psi[base + (f << 4)] = make_float2(x, y);
        }
    }
}

// P3: pairs (l*7+5, l*7+6) @ bits 3..0 ; rotated float4 16-amp consecutive tiles
__device__ __forceinline__ void passP3(float2* psi, const float4* smats, int l, int t){
    float4* p4 = reinterpret_cast<float4*>(psi);
    const int rot = t & 7;
    #pragma unroll 1
    for (int tt = 0; tt < DIM/16/NT; tt++){
        int tile = t + NT*tt;
        u64 amp[16];
        #pragma unroll
        for (int r = 0; r < 8; r++){
            int rr = (r + rot) & 7;
            float4 q = p4[tile*8 + rr];
            amp[2*rr]   = pk2(q.x, q.y);
            amp[2*rr+1] = pk2(q.z, q.w);
        }
        applyTile(amp, smats, l*7 + 5, l*7 + 6);
        #pragma unroll
        for (int r = 0; r < 8; r++){
            int rr = (r + rot) & 7;
            float l0,h0,l1,h1;
            upk2(amp[2*rr],   l0, h0);
            upk2(amp[2*rr+1], l1, h1);
            p4[tile*8 + rr] = make_float4(l0, h0, l1, h1);
        }
    }
}

// P3 for layer 2: apply, then fold final-perm measurement in registers (no stores).
__device__ __forceinline__ void passP3meas(float2* psi, const float4* smats, int t, float* zs){
    float4* p4 = reinterpret_cast<float4*>(psi);
    const int rot = t & 7;
    #pragma unroll 1
    for (int tt = 0; tt < DIM/16/NT; tt++){
        int tile = t + NT*tt;
        u64 amp[16];
        #pragma unroll
        for (int r = 0; r < 8; r++){
            int rr = (r + rot) & 7;
            float4 q = p4[tile*8 + rr];
            amp[2*rr]   = pk2(q.x, q.y);
            amp[2*rr+1] = pk2(q.z, q.w);
        }
        applyTile(amp, smats, 2*7 + 5, 2*7 + 6);
        #pragma unroll
        for (int f = 0; f < 16; f++){
            float x, y; upk2(amp[f], x, y);
            float pr = x*x + y*y;
            unsigned pbits = __float_as_uint(pr);
            unsigned o = (unsigned)pfwd((tile << 4) | f);
            #pragma unroll
            for (int w = 0; w < NW; w++){
                unsigned m = (o << (18 + w)) & 0x80000000u;   // bit (13-w) -> sign
                zs[w] += __uint_as_float(pbits ^ m);
            }
        }
    }
}

// materialize CNOT-ring permutation: whole-CTA register staging (32 amps/thread)
__device__ __forceinline__ void permpass(float2* psi, int t){
    float2 tmp[DIM/NT];
    #pragma unroll
    for (int j = 0; j < DIM/NT; j++)
        tmp[j] = psi[pinv(t + NT*j)];
    __syncthreads();
    #pragma unroll
    for (int j = 0; j < DIM/NT; j++)
        psi[t + NT*j] = tmp[j];
}

// ---------------- main kernel ----------------

__global__ void __launch_bounds__(NT, 1)
qsim_kernel(const float* __restrict__ sr, const float* __restrict__ si,
            const float* __restrict__ hw, const float* __restrict__ hb,
            float* __restrict__ out)
{
    extern __shared__ float2 sm[];
    float2* psi = sm;
    float4* smats = reinterpret_cast<float4*>(sm + DIM);
    const int t = threadIdx.x;
    const int b = blockIdx.x;

    // stage gate matrices into smem (broadcast source for all passes)
    if (t < 21*16) smats[t] = (&g_mats[0][0])[t];

    // ---- layer 0 P1 fused with global load ----
    {
        const float* srb = sr + (size_t)b * DIM;
        const float* sib = si + (size_t)b * DIM;
        #pragma unroll 1
        for (int j = 0; j < DIM/16/NT; j++){
            int gid = t + NT*j;
            u64 amp[16];
            #pragma unroll
            for (int f = 0; f < 16; f++){
                float re = __ldg(srb + (f << 10) + gid);
                float im = __ldg(sib + (f << 10) + gid);
                amp[f] = pk2(re, im);
            }
            __syncthreads();           // smats staged (only needed once; j loop is 2 iters)
            applyTile(amp, smats, 0, 1);
            #pragma unroll
            for (int f = 0; f < 16; f++){
                float x, y; upk2(amp[f], x, y);
                psi[(f << 10) + gid] = make_float2(x, y);
            }
        }
    }
    __syncthreads();
    passP2(psi, smats, 0, t);  __syncthreads();
    passP2b(psi, smats, 0, t); __syncthreads();
    passP3(psi, smats, 0, t);  __syncthreads();
    permpass(psi, t);          __syncthreads();

    passP1(psi, smats, 1, t);  __syncthreads();
    passP2(psi, smats, 1, t);  __syncthreads();
    passP2b(psi, smats, 1, t); __syncthreads();
    passP3(psi, smats, 1, t);  __syncthreads();
    permpass(psi, t);          __syncthreads();

    passP1(psi, smats, 2, t);  __syncthreads();
    passP2(psi, smats, 2, t);  __syncthreads();
    passP2b(psi, smats, 2, t); __syncthreads();

    // ---- layer 2 P3 + measurement (final perm folded via pfwd) ----
    float zs[NW];
    #pragma unroll
    for (int w = 0; w < NW; w++) zs[w] = 0.f;
    passP3meas(psi, smats, t, zs);

    // warp reduce
    #pragma unroll
    for (int off = 16; off > 0; off >>= 1)
        #pragma unroll
        for (int w = 0; w < NW; w++)
            zs[w] += __shfl_down_sync(0xffffffffu, zs[w], off);
    __syncthreads();                       // all psi reads done; reuse as scratch
    float* red = (float*)psi;
    const int NWARP = NT/32;
    int lane = t & 31, wid = t >> 5;
    if (lane == 0){
        #pragma unroll
        for (int w = 0; w < NW; w++) red[w*NWARP + wid] = zs[w];
    }
    __syncthreads();
    if (t == 0){
        float acc = __ldg(hb);
        #pragma unroll
        for (int w = 0; w < NW; w++){
            float f = 0.f;
            #pragma unroll
            for (int r = 0; r < NWARP; r++) f += red[w*NWARP + r];
            acc += f * __ldg(hw + w);
        }
        out[b] = acc;
    }
}

// ---------------- launch ----------------

extern "C" void kernel_launch(void* const* d_in, const int* in_sizes, int n_in,
                              void* d_out, int out_size)
{
    const float* sr = (const float*)d_in[0];
    const float* si = (const float*)d_in[1];
    const float* vp = (const float*)d_in[2];
    const float* hw = (const float*)d_in[3];
    const float* hb = (const float*)d_in[4];
    float* out = (float*)d_out;

    const int SMEM = DIM*sizeof(float2) + 21*16*sizeof(float4);   // 131072 + 5376

    cudaFuncSetAttribute(qsim_kernel, cudaFuncAttributeMaxDynamicSharedMemorySize, SMEM);

    setup_mats<<<1, 32>>>(vp);

    int B = in_sizes[0] / DIM;
    qsim_kernel<<<B, NT, SMEM>>>(sr, si, hw, hb, out);
}

// round 5
// speedup vs baseline: 1.3539x; 1.3539x over previous
#include <cuda_runtime.h>

// QuantumRegression: 1024 x 14-qubit statevector sim, 3 layers (Rot per wire + CNOT ring),
// <Z_w> features, linear head.
//
// R5: NT=512, gates applied as per-wire 2x2 complex matrices (16 regs each, one live at a
// time) instead of fused 4x4 kron (64 regs) -> no spills at the 128-reg/thread cap.
// Pass structure per layer: P1 bits 13..10 | P2 bits 9..6 | P2b bits 5,4 | P3 bits 3..0.
// CNOT ring perm: register staging between layers; final perm folded into measurement.
// Layer-0 P1 fused with gmem load; layer-2 P3 fused with measurement.

#define NW   14
#define DIM  16384
#define NT   512

typedef unsigned long long u64;

__device__ float4 g_m2[3*NW][4];   // per-wire 2x2: row-major, each entry {ur, ur, -ui, ui}

// ---------------- setup: build per-wire 2x2 gate matrices ----------------

struct cpx { float re, im; };
__device__ __forceinline__ cpx cmul(cpx a, cpx b){
    cpx r; r.re = a.re*b.re - a.im*b.im; r.im = a.re*b.im + a.im*b.re; return r;
}

__device__ void rotmat(const float* p, cpx U[2][2]){
    float cx = cosf(0.5f*p[0]), sx = sinf(0.5f*p[0]);
    float cy = cosf(0.5f*p[1]), sy = sinf(0.5f*p[1]);
    float cz = cosf(0.5f*p[2]), sz = sinf(0.5f*p[2]);
    cpx r00 = { cy*cx,  sy*sx};
    cpx r01 = {-sy*cx, -cy*sx};
    cpx r10 = { sy*cx, -cy*sx};
    cpx r11 = { cy*cx, -sy*sx};
    cpx e0 = {cz, -sz}, e1 = {cz, sz};
    U[0][0] = cmul(e0, r00); U[0][1] = cmul(e0, r01);
    U[1][0] = cmul(e1, r10); U[1][1] = cmul(e1, r11);
}

__global__ void setup_mats(const float* __restrict__ vp){
    int g = threadIdx.x;
    if (g >= 3*NW) return;
    cpx U[2][2];
    rotmat(vp + g*3, U);
    #pragma unroll
    for (int i = 0; i < 2; i++)
    #pragma unroll
    for (int j = 0; j < 2; j++)
        g_m2[g][2*i + j] = make_float4(U[i][j].re, U[i][j].re, -U[i][j].im, U[i][j].im);
}

// ---------------- packed f32x2 helpers ----------------

__device__ __forceinline__ u64 pk2(float lo, float hi){
    u64 r; asm("mov.b64 %0, {%1,%2};" : "=l"(r) : "f"(lo), "f"(hi)); return r;
}
__device__ __forceinline__ void upk2(u64 v, float& lo, float& hi){
    asm("mov.b64 {%0,%1}, %2;" : "=f"(lo), "=f"(hi) : "l"(v));
}
__device__ __forceinline__ u64 swp2(u64 v){
    u64 r;
    asm("{ .reg .b32 a,b; mov.b64 {a,b}, %1; mov.b64 %0, {b,a}; }" : "=l"(r) : "l"(v));
    return r;
}
__device__ __forceinline__ u64 f2(u64 a, u64 b, u64 c){
    u64 r; asm("fma.rn.f32x2 %0, %1, %2, %3;" : "=l"(r) : "l"(a), "l"(b), "l"(c)); return r;
}
__device__ __forceinline__ u64 m2(u64 a, u64 b){
    u64 r; asm("mul.rn.f32x2 %0, %1, %2;" : "=l"(r) : "l"(a), "l"(b)); return r;
}

struct Mat2 { u64 u[4], n[4]; };    // 16 registers

// broadcast-load a wire matrix from smem
__device__ __forceinline__ void loadM2(Mat2& M, const float4* smats, int wire){
    #pragma unroll
    for (int e = 0; e < 4; e++){
        float4 f = smats[wire*4 + e];
        M.u[e] = pk2(f.x, f.y);
        M.n[e] = pk2(f.z, f.w);
    }
}

// in-place 2x2 complex gate on amp pair (i0 = |0> side, i1 = |1> side)
__device__ __forceinline__ void apply2(const Mat2& M, u64* amp, int i0, int i1){
    u64 v0 = amp[i0], v1 = amp[i1];
    u64 s0 = swp2(v0), s1 = swp2(v1);
    u64 a = m2(M.u[0], v0);
    a = f2(M.n[0], s0, a);
    a = f2(M.u[1], v1, a);
    a = f2(M.n[1], s1, a);
    u64 b = m2(M.u[2], v0);
    b = f2(M.n[2], s0, b);
    b = f2(M.u[3], v1, b);
    b = f2(M.n[3], s1, b);
    amp[i0] = a; amp[i1] = b;
}

// apply 4 wires (wbase..wbase+3) on f-bits 3..0 of a 16-amp register tile
__device__ __forceinline__ void applyTile16(u64* amp, const float4* smats, int wbase){
    #pragma unroll
    for (int k = 3; k >= 0; k--){          // f-bit k <-> wire wbase + (3-k)
        Mat2 M; loadM2(M, smats, wbase + (3 - k));
        const int bit = 1 << k;
        #pragma unroll
        for (int p = 0; p < 16; p++)
            if (!(p & bit))
                apply2(M, amp, p, p | bit);
    }
}

// ---------------- CNOT-ring permutation (GF2 linear) ----------------
__device__ __forceinline__ int pfwd(int i){
    int y = i;
    y ^= y >> 1; y ^= y >> 2; y ^= y >> 4; y ^= y >> 8;
    return (y & 0x1FFF) ^ ((((y ^ (i >> 13)) & 1) << 13));
}
__device__ __forceinline__ int pinv(int o){
    int t = o ^ (o >> 1);
    return (t & 0x1FFF) ^ (o & 0x2000) ^ ((o & 1) ? 0x3000 : 0);
}

// ---------------- passes ----------------

// P1: wires l*14+0..3 @ bits 13..10
__device__ __forceinline__ void passP1(float2* psi, const float4* smats, int l, int t){
    #pragma unroll 1
    for (int j = 0; j < DIM/16/NT; j++){
        int gid = t + NT*j;
        u64 amp[16];
        #pragma unroll
        for (int f = 0; f < 16; f++){
            float2 a = psi[(f << 10) | gid];
            amp[f] = pk2(a.x, a.y);
        }
        applyTile16(amp, smats, l*NW + 0);
        #pragma unroll
        for (int f = 0; f < 16; f++){
            float x, y; upk2(amp[f], x, y);
            psi[(f << 10) | gid] = make_float2(x, y);
        }
    }
}

// P2: wires l*14+4..7 @ bits 9..6
__device__ __forceinline__ void passP2(float2* psi, const float4* smats, int l, int t){
    #pragma unroll 1
    for (int j = 0; j < DIM/16/NT; j++){
        int g = t + NT*j;
        int base = ((g >> 6) << 10) | (g & 63);
        u64 amp[16];
        #pragma unroll
        for (int f = 0; f < 16; f++){
            float2 a = psi[base + (f << 6)];
            amp[f] = pk2(a.x, a.y);
        }
        applyTile16(amp, smats, l*NW + 4);
        #pragma unroll
        for (int f = 0; f < 16; f++){
            float x, y; upk2(amp[f], x, y);
            psi[base + (f << 6)] = make_float2(x, y);
        }
    }
}

// P2b: wires l*14+8,9 @ bits 5,4 : 4-amp tiles, both matrices live (32 regs)
__device__ __forceinline__ void passP2b(float2* psi, const float4* smats, int l, int t){
    Mat2 Ma, Mb;
    loadM2(Ma, smats, l*NW + 8);
    loadM2(Mb, smats, l*NW + 9);
    #pragma unroll 1
    for (int j = 0; j < DIM/4/NT; j++){
        int g = t + NT*j;
        int base = ((g >> 4) << 6) | (g & 15);
        u64 a4[4];
        #pragma unroll
        for (int f = 0; f < 4; f++){
            float2 a = psi[base + (f << 4)];
            a4[f] = pk2(a.x, a.y);
        }
        apply2(Ma, a4, 0, 2); apply2(Ma, a4, 1, 3);   // bit 5 (f-bit 1) = wire 8
        apply2(Mb, a4, 0, 1); apply2(Mb, a4, 2, 3);   // bit 4 (f-bit 0) = wire 9
        #pragma unroll
        for (int f = 0; f < 4; f++){
            float x, y; upk2(a4[f], x, y);
            psi[base + (f << 4)] = make_float2(x, y);
        }
    }
}

// P3: wires l*14+10..13 @ bits 3..0 ; rotated float4 16-amp consecutive tiles
__device__ __forceinline__ void passP3(float2* psi, const float4* smats, int l, int t){
    float4* p4 = reinterpret_cast<float4*>(psi);
    const int rot = t & 7;
    #pragma unroll 1
    for (int tt = 0; tt < DIM/16/NT; tt++){
        int tile = t + NT*tt;
        u64 amp[16];
        #pragma unroll
        for (int r = 0; r < 8; r++){
            int rr = (r + rot) & 7;
            float4 q = p4[tile*8 + rr];
            amp[2*rr]   = pk2(q.x, q.y);
            amp[2*rr+1] = pk2(q.z, q.w);
        }
        applyTile16(amp, smats, l*NW + 10);
        #pragma unroll
        for (int r = 0; r < 8; r++){
            int rr = (r + rot) & 7;
            float l0,h0,l1,h1;
            upk2(amp[2*rr],   l0, h0);
            upk2(amp[2*rr+1], l1, h1);
            p4[tile*8 + rr] = make_float4(l0, h0, l1, h1);
        }
    }
}

// P3 for layer 2: apply, then fold final-perm measurement in registers (no stores).
__device__ __forceinline__ void passP3meas(float2* psi, const float4* smats, int t, float* zs){
    float4* p4 = reinterpret_cast<float4*>(psi);
    const int rot = t & 7;
    #pragma unroll 1
    for (int tt = 0; tt < DIM/16/NT; tt++){
        int tile = t + NT*tt;
        u64 amp[16];
        #pragma unroll
        for (int r = 0; r < 8; r++){
            int rr = (r + rot) & 7;
            float4 q = p4[tile*8 + rr];
            amp[2*rr]   = pk2(q.x, q.y);
            amp[2*rr+1] = pk2(q.z, q.w);
        }
        applyTile16(amp, smats, 2*NW + 10);
        #pragma unroll
        for (int f = 0; f < 16; f++){
            float x, y; upk2(amp[f], x, y);
            float pr = x*x + y*y;
            unsigned pbits = __float_as_uint(pr);
            unsigned o = (unsigned)pfwd((tile << 4) | f);
            #pragma unroll
            for (int w = 0; w < NW; w++){
                unsigned m = (o << (18 + w)) & 0x80000000u;   // bit (13-w) -> sign
                zs[w] += __uint_as_float(pbits ^ m);
            }
        }
    }
}

// materialize CNOT-ring permutation: whole-CTA register staging (32 amps/thread)
__device__ __forceinline__ void permpass(float2* psi, int t){
    float2 tmp[DIM/NT];
    #pragma unroll
    for (int j = 0; j < DIM/NT; j++)
        tmp[j] = psi[pinv(t + NT*j)];
    __syncthreads();
    #pragma unroll
    for (int j = 0; j < DIM/NT; j++)
        psi[t + NT*j] = tmp[j];
}

// ---------------- main kernel ----------------

__global__ void __launch_bounds__(NT, 1)
qsim_kernel(const float* __restrict__ sr, const float* __restrict__ si,
            const float* __restrict__ hw, const float* __restrict__ hb,
            float* __restrict__ out)
{
    extern __shared__ float2 sm[];
    float2* psi = sm;
    float4* smats = reinterpret_cast<float4*>(sm + DIM);
    const int t = threadIdx.x;
    const int b = blockIdx.x;

    // stage gate matrices into smem (broadcast source for all passes)
    if (t < 3*NW*4) smats[t] = (&g_m2[0][0])[t];
    __syncthreads();

    // ---- layer 0 P1 fused with global load ----
    {
        const float* srb = sr + (size_t)b * DIM;
        const float* sib = si + (size_t)b * DIM;
        #pragma unroll 1
        for (int j = 0; j < DIM/16/NT; j++){
            int gid = t + NT*j;
            u64 amp[16];
            #pragma unroll
            for (int f = 0; f < 16; f++){
                float re = __ldg(srb + (f << 10) + gid);
                float im = __ldg(sib + (f << 10) + gid);
                amp[f] = pk2(re, im);
            }
            applyTile16(amp, smats, 0);
            #pragma unroll
            for (int f = 0; f < 16; f++){
                float x, y; upk2(amp[f], x, y);
                psi[(f << 10) + gid] = make_float2(x, y);
            }
        }
    }
    __syncthreads();
    passP2(psi, smats, 0, t);  __syncthreads();
    passP2b(psi, smats, 0, t); __syncthreads();
    passP3(psi, smats, 0, t);  __syncthreads();
    permpass(psi, t);          __syncthreads();

    passP1(psi, smats, 1, t);  __syncthreads();
    passP2(psi, smats, 1, t);  __syncthreads();
    passP2b(psi, smats, 1, t); __syncthreads();
    passP3(psi, smats, 1, t);  __syncthreads();
    permpass(psi, t);          __syncthreads();

    passP1(psi, smats, 2, t);  __syncthreads();
    passP2(psi, smats, 2, t);  __syncthreads();
    passP2b(psi, smats, 2, t); __syncthreads();

    // ---- layer 2 P3 + measurement (final perm folded via pfwd) ----
    float zs[NW];
    #pragma unroll
    for (int w = 0; w < NW; w++) zs[w] = 0.f;
    passP3meas(psi, smats, t, zs);

    // warp reduce
    #pragma unroll
    for (int off = 16; off > 0; off >>= 1)
        #pragma unroll
        for (int w = 0; w < NW; w++)
            zs[w] += __shfl_down_sync(0xffffffffu, zs[w], off);
    __syncthreads();                       // all psi reads done; reuse as scratch
    float* red = (float*)psi;
    const int NWARP = NT/32;
    int lane = t & 31, wid = t >> 5;
    if (lane == 0){
        #pragma unroll
        for (int w = 0; w < NW; w++) red[w*NWARP + wid] = zs[w];
    }
    __syncthreads();
    if (t == 0){
        float acc = __ldg(hb);
        #pragma unroll
        for (int w = 0; w < NW; w++){
            float f = 0.f;
            #pragma unroll
            for (int r = 0; r < NWARP; r++) f += red[w*NWARP + r];
            acc += f * __ldg(hw + w);
        }
        out[b] = acc;
    }
}

// ---------------- launch ----------------

extern "C" void kernel_launch(void* const* d_in, const int* in_sizes, int n_in,
                              void* d_out, int out_size)
{
    const float* sr = (const float*)d_in[0];
    const float* si = (const float*)d_in[1];
    const float* vp = (const float*)d_in[2];
    const float* hw = (const float*)d_in[3];
    const float* hb = (const float*)d_in[4];
    float* out = (float*)d_out;

    const int SMEM = DIM*sizeof(float2) + 3*NW*4*sizeof(float4);   // 131072 + 2688

    cudaFuncSetAttribute(qsim_kernel, cudaFuncAttributeMaxDynamicSharedMemorySize, SMEM);

    setup_mats<<<1, 64>>>(vp);

    int B = in_sizes[0] / DIM;
    qsim_kernel<<<B, NT, SMEM>>>(sr, si, hw, hb, out);
}

// round 6
// speedup vs baseline: 3.0966x; 2.2871x over previous
#include <cuda_runtime.h>

// QuantumRegression: 1024 x 14-qubit statevector sim, 3 layers (Rot per wire + CNOT ring),
// <Z_w> features, linear head.
//
// R6: frame-tracked CNOT-ring permutations (never materialized). After l rings the amp at
// physical address a has logical index P^l(a); layer-l gate tiles gather at pinv^l-mapped
// addresses (compile-time constexpr direction masks). Measurement folds P^3, which against
// layer-2's P^-2 addressing reduces to a single pfwd. P3 passes at l>=1 use an XOR stagger
// (f = m ^ u) + row/col-swapped matrices to stay shared-memory bank-conflict-free.
// NT=512, 2x2 gates (16 regs live), 12 smem round trips total.

#define NW   14
#define DIM  16384
#define NT   512

typedef unsigned long long u64;

__device__ float4 g_m2[3*NW][4];   // per-wire 2x2: row-major, each entry {ur, ur, -ui, ui}

// ---------------- setup: build per-wire 2x2 gate matrices ----------------

struct cpx { float re, im; };
__device__ __forceinline__ cpx cmul(cpx a, cpx b){
    cpx r; r.re = a.re*b.re - a.im*b.im; r.im = a.re*b.im + a.im*b.re; return r;
}

__device__ void rotmat(const float* p, cpx U[2][2]){
    float cx = cosf(0.5f*p[0]), sx = sinf(0.5f*p[0]);
    float cy = cosf(0.5f*p[1]), sy = sinf(0.5f*p[1]);
    float cz = cosf(0.5f*p[2]), sz = sinf(0.5f*p[2]);
    cpx r00 = { cy*cx,  sy*sx};
    cpx r01 = {-sy*cx, -cy*sx};
    cpx r10 = { sy*cx, -cy*sx};
    cpx r11 = { cy*cx, -sy*sx};
    cpx e0 = {cz, -sz}, e1 = {cz, sz};
    U[0][0] = cmul(e0, r00); U[0][1] = cmul(e0, r01);
    U[1][0] = cmul(e1, r10); U[1][1] = cmul(e1, r11);
}

__global__ void setup_mats(const float* __restrict__ vp){
    int g = threadIdx.x;
    if (g >= 3*NW) return;
    cpx U[2][2];
    rotmat(vp + g*3, U);
    #pragma unroll
    for (int i = 0; i < 2; i++)
    #pragma unroll
    for (int j = 0; j < 2; j++)
        g_m2[g][2*i + j] = make_float4(U[i][j].re, U[i][j].re, -U[i][j].im, U[i][j].im);
}

// ---------------- packed f32x2 helpers ----------------

__device__ __forceinline__ u64 pk2(float lo, float hi){
    u64 r; asm("mov.b64 %0, {%1,%2};" : "=l"(r) : "f"(lo), "f"(hi)); return r;
}
__device__ __forceinline__ void upk2(u64 v, float& lo, float& hi){
    asm("mov.b64 {%0,%1}, %2;" : "=f"(lo), "=f"(hi) : "l"(v));
}
__device__ __forceinline__ u64 swp2(u64 v){
    u64 r;
    asm("{ .reg .b32 a,b; mov.b64 {a,b}, %1; mov.b64 %0, {b,a}; }" : "=l"(r) : "l"(v));
    return r;
}
__device__ __forceinline__ u64 f2(u64 a, u64 b, u64 c){
    u64 r; asm("fma.rn.f32x2 %0, %1, %2, %3;" : "=l"(r) : "l"(a), "l"(b), "l"(c)); return r;
}
__device__ __forceinline__ u64 m2(u64 a, u64 b){
    u64 r; asm("mul.rn.f32x2 %0, %1, %2;" : "=l"(r) : "l"(a), "l"(b)); return r;
}

struct Mat2 { u64 u[4], n[4]; };    // 16 registers

// broadcast-load a wire matrix from smem; sw3=3 loads the row/col-swapped gate (e ^ 3)
__device__ __forceinline__ void loadM2S(Mat2& M, const float4* smats, int wire, int sw3){
    #pragma unroll
    for (int e = 0; e < 4; e++){
        float4 f = smats[wire*4 + (e ^ sw3)];
        M.u[e] = pk2(f.x, f.y);
        M.n[e] = pk2(f.z, f.w);
    }
}

// in-place 2x2 complex gate on amp pair (i0 = |0> side, i1 = |1> side)
__device__ __forceinline__ void apply2(const Mat2& M, u64* amp, int i0, int i1){
    u64 v0 = amp[i0], v1 = amp[i1];
    u64 s0 = swp2(v0), s1 = swp2(v1);
    u64 a = m2(M.u[0], v0);
    a = f2(M.n[0], s0, a);
    a = f2(M.u[1], v1, a);
    a = f2(M.n[1], s1, a);
    u64 b = m2(M.u[2], v0);
    b = f2(M.n[2], s0, b);
    b = f2(M.u[3], v1, b);
    b = f2(M.n[3], s1, b);
    amp[i0] = a; amp[i1] = b;
}

// apply 4 wires (wbase..wbase+3) on m-bits 3..0 of a 16-amp register tile.
// u: logical f = m ^ u (stagger); a set u-bit means 0/1 roles swap -> swapped matrix.
__device__ __forceinline__ void applyTile16S(u64* amp, const float4* smats, int wbase, int u){
    #pragma unroll
    for (int k = 3; k >= 0; k--){          // m-bit k <-> wire wbase + (3-k)
        Mat2 M; loadM2S(M, smats, wbase + (3 - k), ((u >> k) & 1) * 3);
        const int bit = 1 << k;
        #pragma unroll
        for (int p = 0; p < 16; p++)
            if (!(p & bit))
                apply2(M, amp, p, p | bit);
    }
}

// ---------------- CNOT-ring permutation (GF2 linear, constexpr-foldable) ----------------
__host__ __device__ __forceinline__ constexpr int cpfwd(int i){
    int y = i;
    y ^= y >> 1; y ^= y >> 2; y ^= y >> 4; y ^= y >> 8;
    return (y & 0x1FFF) ^ ((((y ^ (i >> 13)) & 1) << 13));
}
__host__ __device__ __forceinline__ constexpr int cpinv(int o){
    int t = o ^ (o >> 1);
    return (t & 0x1FFF) ^ (o & 0x2000) ^ ((o & 1) ? 0x3000 : 0);
}
template<int L>
__host__ __device__ __forceinline__ constexpr int pinvL(int x){
    return (L == 0) ? x : (L == 1) ? cpinv(x) : cpinv(cpinv(x));
}

// ---------------- passes ----------------

// 4-wire pass at logical bits S+3..S (S>0), layer L (frame P^L). Conflict-free as-is.
template<int L, int S>
__device__ __forceinline__ void passG(float2* psi, const float4* smats, int t){
    #pragma unroll 1
    for (int j = 0; j < DIM/16/NT; j++){
        int y = t + NT*j;
        int x = ((y >> S) << (S+4)) | (y & ((1 << S) - 1));
        int base = pinvL<L>(x);
        u64 amp[16];
        #pragma unroll
        for (int f = 0; f < 16; f++){
            float2 a = psi[base ^ pinvL<L>(f << S)];
            amp[f] = pk2(a.x, a.y);
        }
        applyTile16S(amp, smats, L*NW + (10 - S), 0);
        #pragma unroll
        for (int f = 0; f < 16; f++){
            float xx, yy; upk2(amp[f], xx, yy);
            psi[base ^ pinvL<L>(f << S)] = make_float2(xx, yy);
        }
    }
}

// 2-wire pass at logical bits 5,4 (wires 8,9), layer L.
template<int L>
__device__ __forceinline__ void passP2b(float2* psi, const float4* smats, int t){
    Mat2 Ma, Mb;
    loadM2S(Ma, smats, L*NW + 8, 0);
    loadM2S(Mb, smats, L*NW + 9, 0);
    #pragma unroll 1
    for (int j = 0; j < DIM/4/NT; j++){
        int y = t + NT*j;
        int x = ((y >> 4) << 6) | (y & 15);
        int base = pinvL<L>(x);
        u64 a4[4];
        #pragma unroll
        for (int f = 0; f < 4; f++){
            float2 a = psi[base ^ pinvL<L>(f << 4)];
            a4[f] = pk2(a.x, a.y);
        }
        apply2(Ma, a4, 0, 2); apply2(Ma, a4, 1, 3);   // logical bit 5 = wire 8
        apply2(Mb, a4, 0, 1); apply2(Mb, a4, 2, 3);   // logical bit 4 = wire 9
        #pragma unroll
        for (int f = 0; f < 4; f++){
            float xx, yy; upk2(a4[f], xx, yy);
            psi[base ^ pinvL<L>(f << 4)] = make_float2(xx, yy);
        }
    }
}

// stagger offset u for P3 passes: u = A_L^{-1}((lane&15) ^ base_low4)
template<int L>
__device__ __forceinline__ int p3stagger(int t){
    int r4 = t & 15;
    if (L == 0) return r4;
    if (L == 1){ int v = r4 ^ ((t & 1) << 3); return (v ^ (v>>1) ^ (v>>2) ^ (v>>3)) & 15; }
    int v = r4 ^ ((t & 3) << 2); return (v ^ (v >> 2)) & 15;
}

// 4-wire pass at logical bits 3..0 (wires 10..13), layer L; MEAS folds P^3 measurement.
template<int L, bool MEAS>
__device__ __forceinline__ void passP3G(float2* psi, const float4* smats, int t, float* zs){
    const int u = p3stagger<L>(t);
    const int uoff = pinvL<L>(u);
    #pragma unroll 1
    for (int tt = 0; tt < DIM/16/NT; tt++){
        int y = t + NT*tt;                        // 10-bit tile index
        int base = pinvL<L>(y << 4) ^ uoff;
        u64 amp[16];
        #pragma unroll
        for (int m = 0; m < 16; m++){
            float2 a = psi[base ^ pinvL<L>(m)];
            amp[m] = pk2(a.x, a.y);
        }
        applyTile16S(amp, smats, L*NW + 10, u);
        if (!MEAS){
            #pragma unroll
            for (int m = 0; m < 16; m++){
                float xx, yy; upk2(amp[m], xx, yy);
                psi[base ^ pinvL<L>(m)] = make_float2(xx, yy);
            }
        } else {
            // logical index o = P^3(addr) = pfwd((y<<4) ^ m ^ u)  [P^3 . P^-2 = P, linear]
            int obase = cpfwd((y << 4) ^ u);
            #pragma unroll
            for (int m = 0; m < 16; m++){
                float xx, yy; upk2(amp[m], xx, yy);
                float pr = xx*xx + yy*yy;
                unsigned pbits = __float_as_uint(pr);
                unsigned o = (unsigned)(obase ^ cpfwd(m));
                #pragma unroll
                for (int w = 0; w < NW; w++){
                    unsigned msk = (o << (18 + w)) & 0x80000000u;   // bit (13-w) -> sign
                    zs[w] += __uint_as_float(pbits ^ msk);
                }
            }
        }
    }
}

// ---------------- main kernel ----------------

__global__ void __launch_bounds__(NT, 1)
qsim_kernel(const float* __restrict__ sr, const float* __restrict__ si,
            const float* __restrict__ hw, const float* __restrict__ hb,
            float* __restrict__ out)
{
    extern __shared__ float2 sm[];
    float2* psi = sm;
    float4* smats = reinterpret_cast<float4*>(sm + DIM);
    const int t = threadIdx.x;
    const int b = blockIdx.x;

    // stage gate matrices into smem (broadcast source for all passes)
    if (t < 3*NW*4) smats[t] = (&g_m2[0][0])[t];
    __syncthreads();

    // ---- layer 0 P1 (wires 0..3, bits 13..10) fused with global load ----
    {
        const float* srb = sr + (size_t)b * DIM;
        const float* sib = si + (size_t)b * DIM;
        #pragma unroll 1
        for (int j = 0; j < DIM/16/NT; j++){
            int gid = t + NT*j;
            u64 amp[16];
            #pragma unroll
            for (int f = 0; f < 16; f++){
                float re = __ldg(srb + (f << 10) + gid);
                float im = __ldg(sib + (f << 10) + gid);
                amp[f] = pk2(re, im);
            }
            applyTile16S(amp, smats, 0, 0);
            #pragma unroll
            for (int f = 0; f < 16; f++){
                float x, y; upk2(amp[f], x, y);
                psi[(f << 10) + gid] = make_float2(x, y);
            }
        }
    }
    __syncthreads();
    passG<0,6>(psi, smats, t);          __syncthreads();
    passP2b<0>(psi, smats, t);          __syncthreads();
    passP3G<0,false>(psi, smats, t, 0); __syncthreads();

    passG<1,10>(psi, smats, t);         __syncthreads();
    passG<1,6>(psi, smats, t);          __syncthreads();
    passP2b<1>(psi, smats, t);          __syncthreads();
    passP3G<1,false>(psi, smats, t, 0); __syncthreads();

    passG<2,10>(psi, smats, t);         __syncthreads();
    passG<2,6>(psi, smats, t);          __syncthreads();
    passP2b<2>(psi, smats, t);          __syncthreads();

    // ---- layer 2 P3 + measurement (P^3 folded) ----
    float zs[NW];
    #pragma unroll
    for (int w = 0; w < NW; w++) zs[w] = 0.f;
    passP3G<2,true>(psi, smats, t, zs);

    // warp reduce
    #pragma unroll
    for (int off = 16; off > 0; off >>= 1)
        #pragma unroll
        for (int w = 0; w < NW; w++)
            zs[w] += __shfl_down_sync(0xffffffffu, zs[w], off);
    __syncthreads();                       // all psi reads done; reuse as scratch
    float* red = (float*)psi;
    const int NWARP = NT/32;
    int lane = t & 31, wid = t >> 5;
    if (lane == 0){
        #pragma unroll
        for (int w = 0; w < NW; w++) red[w*NWARP + wid] = zs[w];
    }
    __syncthreads();
    if (t == 0){
        float acc = __ldg(hb);
        #pragma unroll
        for (int w = 0; w < NW; w++){
            float f = 0.f;
            #pragma unroll
            for (int r = 0; r < NWARP; r++) f += red[w*NWARP + r];
            acc += f * __ldg(hw + w);
        }
        out[b] = acc;
    }
}

// ---------------- launch ----------------

extern "C" void kernel_launch(void* const* d_in, const int* in_sizes, int n_in,
                              void* d_out, int out_size)
{
    const float* sr = (const float*)d_in[0];
    const float* si = (const float*)d_in[1];
    const float* vp = (const float*)d_in[2];
    const float* hw = (const float*)d_in[3];
    const float* hb = (const float*)d_in[4];
    float* out = (float*)d_out;

    const int SMEM = DIM*sizeof(float2) + 3*NW*4*sizeof(float4);   // 131072 + 2688

    cudaFuncSetAttribute(qsim_kernel, cudaFuncAttributeMaxDynamicSharedMemorySize, SMEM);

    setup_mats<<<1, 64>>>(vp);

    int B = in_sizes[0] / DIM;
    qsim_kernel<<<B, NT, SMEM>>>(sr, si, hw, hb, out);
}

// round 7
// speedup vs baseline: 3.6161x; 1.1678x over previous
#include <cuda_runtime.h>

// QuantumRegression: 1024 x 14-qubit statevector sim, 3 layers (Rot per wire + CNOT ring),
// <Z_w> features, linear head.
//
// R7: 3 passes per layer with 32-amp register tiles:
//   A: logical bits 13..9 (wires 0..4)   B: bits 8..4 (wires 5..9)   C: bits 3..0 (wires 10..13)
// Frame-tracked CNOT-ring perms (physical addr = pinv^L(logical)); C uses XOR stagger for
// bank-conflict freedom at L>=1. Measurement folds P^3 and uses a partial Walsh butterfly
// (only 5 wires have amp-varying signs within a 16-amp tile). NT=512, 9 smem round trips.

#define NW   14
#define DIM  16384
#define NT   512

typedef unsigned long long u64;

__device__ float4 g_m2[3*NW][4];   // per-wire 2x2: row-major, each entry {ur, ur, -ui, ui}

// ---------------- setup: build per-wire 2x2 gate matrices ----------------

struct cpx { float re, im; };
__device__ __forceinline__ cpx cmul(cpx a, cpx b){
    cpx r; r.re = a.re*b.re - a.im*b.im; r.im = a.re*b.im + a.im*b.re; return r;
}

__device__ void rotmat(const float* p, cpx U[2][2]){
    float cx = cosf(0.5f*p[0]), sx = sinf(0.5f*p[0]);
    float cy = cosf(0.5f*p[1]), sy = sinf(0.5f*p[1]);
    float cz = cosf(0.5f*p[2]), sz = sinf(0.5f*p[2]);
    cpx r00 = { cy*cx,  sy*sx};
    cpx r01 = {-sy*cx, -cy*sx};
    cpx r10 = { sy*cx, -cy*sx};
    cpx r11 = { cy*cx, -sy*sx};
    cpx e0 = {cz, -sz}, e1 = {cz, sz};
    U[0][0] = cmul(e0, r00); U[0][1] = cmul(e0, r01);
    U[1][0] = cmul(e1, r10); U[1][1] = cmul(e1, r11);
}

__global__ void setup_mats(const float* __restrict__ vp){
    int g = threadIdx.x;
    if (g >= 3*NW) return;
    cpx U[2][2];
    rotmat(vp + g*3, U);
    #pragma unroll
    for (int i = 0; i < 2; i++)
    #pragma unroll
    for (int j = 0; j < 2; j++)
        g_m2[g][2*i + j] = make_float4(U[i][j].re, U[i][j].re, -U[i][j].im, U[i][j].im);
}

// ---------------- packed f32x2 helpers ----------------

__device__ __forceinline__ u64 pk2(float lo, float hi){
    u64 r; asm("mov.b64 %0, {%1,%2};" : "=l"(r) : "f"(lo), "f"(hi)); return r;
}
__device__ __forceinline__ void upk2(u64 v, float& lo, float& hi){
    asm("mov.b64 {%0,%1}, %2;" : "=f"(lo), "=f"(hi) : "l"(v));
}
__device__ __forceinline__ u64 swp2(u64 v){
    u64 r;
    asm("{ .reg .b32 a,b; mov.b64 {a,b}, %1; mov.b64 %0, {b,a}; }" : "=l"(r) : "l"(v));
    return r;
}
__device__ __forceinline__ u64 f2(u64 a, u64 b, u64 c){
    u64 r; asm("fma.rn.f32x2 %0, %1, %2, %3;" : "=l"(r) : "l"(a), "l"(b), "l"(c)); return r;
}
__device__ __forceinline__ u64 m2(u64 a, u64 b){
    u64 r; asm("mul.rn.f32x2 %0, %1, %2;" : "=l"(r) : "l"(a), "l"(b)); return r;
}

struct Mat2 { u64 u[4], n[4]; };    // 16 registers

// broadcast-load a wire matrix from smem; sw3=3 loads the row/col-swapped gate (e ^ 3)
__device__ __forceinline__ void loadM2S(Mat2& M, const float4* smats, int wire, int sw3){
    #pragma unroll
    for (int e = 0; e < 4; e++){
        float4 f = smats[wire*4 + (e ^ sw3)];
        M.u[e] = pk2(f.x, f.y);
        M.n[e] = pk2(f.z, f.w);
    }
}

// in-place 2x2 complex gate on amp pair (i0 = |0> side, i1 = |1> side)
__device__ __forceinline__ void apply2(const Mat2& M, u64* amp, int i0, int i1){
    u64 v0 = amp[i0], v1 = amp[i1];
    u64 s0 = swp2(v0), s1 = swp2(v1);
    u64 a = m2(M.u[0], v0);
    a = f2(M.n[0], s0, a);
    a = f2(M.u[1], v1, a);
    a = f2(M.n[1], s1, a);
    u64 b = m2(M.u[2], v0);
    b = f2(M.n[2], s0, b);
    b = f2(M.u[3], v1, b);
    b = f2(M.n[3], s1, b);
    amp[i0] = a; amp[i1] = b;
}

// apply 5 wires on f-bits 4..0 of a 32-amp register tile (f-bit k <-> logical bit S+k)
template<int L, int S>
__device__ __forceinline__ void applyTile32(u64* amp, const float4* smats){
    #pragma unroll
    for (int k = 4; k >= 0; k--){
        Mat2 M; loadM2S(M, smats, L*NW + (13 - S - k), 0);
        const int bit = 1 << k;
        #pragma unroll
        for (int p = 0; p < 32; p++)
            if (!(p & bit))
                apply2(M, amp, p, p | bit);
    }
}

// apply 4 wires on m-bits 3..0 of a 16-amp tile; u = XOR stagger (swapped matrices)
__device__ __forceinline__ void applyTile16S(u64* amp, const float4* smats, int wbase, int u){
    #pragma unroll
    for (int k = 3; k >= 0; k--){          // m-bit k <-> wire wbase + (3-k)
        Mat2 M; loadM2S(M, smats, wbase + (3 - k), ((u >> k) & 1) * 3);
        const int bit = 1 << k;
        #pragma unroll
        for (int p = 0; p < 16; p++)
            if (!(p & bit))
                apply2(M, amp, p, p | bit);
    }
}

// ---------------- CNOT-ring permutation (GF2 linear, constexpr-foldable) ----------------
__host__ __device__ __forceinline__ constexpr int cpfwd(int i){
    int y = i;
    y ^= y >> 1; y ^= y >> 2; y ^= y >> 4; y ^= y >> 8;
    return (y & 0x1FFF) ^ ((((y ^ (i >> 13)) & 1) << 13));
}
__host__ __device__ __forceinline__ constexpr int cpinv(int o){
    int t = o ^ (o >> 1);
    return (t & 0x1FFF) ^ (o & 0x2000) ^ ((o & 1) ? 0x3000 : 0);
}
template<int L>
__host__ __device__ __forceinline__ constexpr int pinvL(int x){
    return (L == 0) ? x : (L == 1) ? cpinv(x) : cpinv(cpinv(x));
}

// ---------------- passes ----------------

// 5-wire 32-amp pass at logical bits S+4..S, layer L. One tile per thread (NT=512).
template<int L, int S>
__device__ __forceinline__ void passG32(float2* psi, const float4* smats, int t){
    int x = ((t >> S) << (S+5)) | (t & ((1 << S) - 1));
    int base = pinvL<L>(x);
    u64 amp[32];
    #pragma unroll
    for (int f = 0; f < 32; f++){
        float2 a = psi[base ^ pinvL<L>(f << S)];
        amp[f] = pk2(a.x, a.y);
    }
    applyTile32<L, S>(amp, smats);
    #pragma unroll
    for (int f = 0; f < 32; f++){
        float xx, yy; upk2(amp[f], xx, yy);
        psi[base ^ pinvL<L>(f << S)] = make_float2(xx, yy);
    }
}

// stagger offset u for C passes: u = A_L^{-1}((lane&15) ^ base_low4)
template<int L>
__device__ __forceinline__ int p3stagger(int t){
    int r4 = t & 15;
    if (L == 0) return r4;
    if (L == 1){ int v = r4 ^ ((t & 1) << 3); return (v ^ (v>>1) ^ (v>>2) ^ (v>>3)) & 15; }
    int v = r4 ^ ((t & 3) << 2); return (v ^ (v >> 2)) & 15;
}

// 4-wire pass at logical bits 3..0 (wires 10..13), layer L; MEAS folds P^3 measurement.
template<int L, bool MEAS>
__device__ __forceinline__ void passC(float2* psi, const float4* smats, int t, float* zs){
    const int u = p3stagger<L>(t);
    const int uoff = pinvL<L>(u);
    #pragma unroll 1
    for (int tt = 0; tt < DIM/16/NT; tt++){
        int y = t + NT*tt;                        // 10-bit tile index
        int base = pinvL<L>(y << 4) ^ uoff;
        u64 amp[16];
        #pragma unroll
        for (int m = 0; m < 16; m++){
            float2 a = psi[base ^ pinvL<L>(m)];
            amp[m] = pk2(a.x, a.y);
        }
        applyTile16S(amp, smats, L*NW + 10, u);
        if (!MEAS){
            #pragma unroll
            for (int m = 0; m < 16; m++){
                float xx, yy; upk2(amp[m], xx, yy);
                psi[base ^ pinvL<L>(m)] = make_float2(xx, yy);
            }
        } else {
            // logical o = P^3(addr) = cpfwd((y<<4) ^ u ^ m); cpfwd(m) touches bits 3..0 and 13
            int obase = cpfwd((y << 4) ^ u);
            float pr[16];
            #pragma unroll
            for (int m = 0; m < 16; m++){
                float xx, yy; upk2(amp[m], xx, yy);
                pr[m] = xx*xx + yy*yy;
            }
            // partial Walsh butterfly: b0..b3 = bits of m; cpfwd(m) sign bits:
            //   o bit0 = b0^b1^b2^b3 (also o bit13), bit1 = b1^b2^b3, bit2 = b2^b3, bit3 = b3
            float P[8], Mv[8];
            #pragma unroll
            for (int j = 0; j < 8; j++){ P[j] = pr[2*j] + pr[2*j+1]; Mv[j] = pr[2*j] - pr[2*j+1]; }
            float Spar = Mv[0]-Mv[1]-Mv[2]+Mv[3]-Mv[4]+Mv[5]+Mv[6]-Mv[7];
            float PP[4], PM[4];
            #pragma unroll
            for (int k = 0; k < 4; k++){ PP[k] = P[2*k] + P[2*k+1]; PM[k] = P[2*k] - P[2*k+1]; }
            float S123 = PM[0]-PM[1]-PM[2]+PM[3];
            float PPP0 = PP[0]+PP[1], PPP1 = PP[2]+PP[3];
            float S23  = (PP[0]-PP[1]) - (PP[2]-PP[3]);
            float T    = PPP0 + PPP1;
            float S3   = PPP0 - PPP1;
            // wires 1..9: sign constant across tile (obase bits 12..4) applied to T
            #pragma unroll
            for (int w = 1; w <= 9; w++){
                unsigned msk = ((unsigned)obase << (18 + w)) & 0x80000000u;
                zs[w] += __uint_as_float(__float_as_uint(T) ^ msk);
            }
            zs[0]  += __uint_as_float(__float_as_uint(Spar) ^ (((unsigned)obase << 18) & 0x80000000u)); // bit13
            zs[13] += __uint_as_float(__float_as_uint(Spar) ^ (((unsigned)obase << 31) & 0x80000000u)); // bit0
            zs[12] += __uint_as_float(__float_as_uint(S123) ^ (((unsigned)obase << 30) & 0x80000000u)); // bit1
            zs[11] += __uint_as_float(__float_as_uint(S23)  ^ (((unsigned)obase << 29) & 0x80000000u)); // bit2
            zs[10] += __uint_as_float(__float_as_uint(S3)   ^ (((unsigned)obase << 28) & 0x80000000u)); // bit3
        }
    }
}

// ---------------- main kernel ----------------

__global__ void __launch_bounds__(NT, 1)
qsim_kernel(const float* __restrict__ sr, const float* __restrict__ si,
            const float* __restrict__ hw, const float* __restrict__ hb,
            float* __restrict__ out)
{
    extern __shared__ float2 sm[];
    float2* psi = sm;
    float4* smats = reinterpret_cast<float4*>(sm + DIM);
    const int t = threadIdx.x;
    const int b = blockIdx.x;

    // stage gate matrices into smem (broadcast source for all passes)
    if (t < 3*NW*4) smats[t] = (&g_m2[0][0])[t];
    __syncthreads();

    // ---- layer 0 pass A (wires 0..4, bits 13..9) fused with global load ----
    {
        const float* srb = sr + (size_t)b * DIM;
        const float* sib = si + (size_t)b * DIM;
        u64 amp[32];
        #pragma unroll
        for (int f = 0; f < 32; f++){
            float re = __ldg(srb + (f << 9) + t);
            float im = __ldg(sib + (f << 9) + t);
            amp[f] = pk2(re, im);
        }
        applyTile32<0, 9>(amp, smats);
        #pragma unroll
        for (int f = 0; f < 32; f++){
            float x, y; upk2(amp[f], x, y);
            psi[(f << 9) + t] = make_float2(x, y);
        }
    }
    __syncthreads();
    passG32<0,4>(psi, smats, t);     __syncthreads();
    passC<0,false>(psi, smats, t, 0); __syncthreads();

    passG32<1,9>(psi, smats, t);     __syncthreads();
    passG32<1,4>(psi, smats, t);     __syncthreads();
    passC<1,false>(psi, smats, t, 0); __syncthreads();

    passG32<2,9>(psi, smats, t);     __syncthreads();
    passG32<2,4>(psi, smats, t);     __syncthreads();

    // ---- layer 2 pass C + measurement (P^3 folded) ----
    float zs[NW];
    #pragma unroll
    for (int w = 0; w < NW; w++) zs[w] = 0.f;
    passC<2,true>(psi, smats, t, zs);

    // warp reduce
    #pragma unroll
    for (int off = 16; off > 0; off >>= 1)
        #pragma unroll
        for (int w = 0; w < NW; w++)
            zs[w] += __shfl_down_sync(0xffffffffu, zs[w], off);
    __syncthreads();                       // all psi reads done; reuse as scratch
    float* red = (float*)psi;
    const int NWARP = NT/32;
    int lane = t & 31, wid = t >> 5;
    if (lane == 0){
        #pragma unroll
        for (int w = 0; w < NW; w++) red[w*NWARP + wid] = zs[w];
    }
    __syncthreads();
    if (t == 0){
        float acc = __ldg(hb);
        #pragma unroll
        for (int w = 0; w < NW; w++){
            float f = 0.f;
            #pragma unroll
            for (int r = 0; r < NWARP; r++) f += red[w*NWARP + r];
            acc += f * __ldg(hw + w);
        }
        out[b] = acc;
    }
}

// ---------------- launch ----------------

extern "C" void kernel_launch(void* const* d_in, const int* in_sizes, int n_in,
                              void* d_out, int out_size)
{
    const float* sr = (const float*)d_in[0];
    const float* si = (const float*)d_in[1];
    const float* vp = (const float*)d_in[2];
    const float* hw = (const float*)d_in[3];
    const float* hb = (const float*)d_in[4];
    float* out = (float*)d_out;

    const int SMEM = DIM*sizeof(float2) + 3*NW*4*sizeof(float4);   // 131072 + 2688

    cudaFuncSetAttribute(qsim_kernel, cudaFuncAttributeMaxDynamicSharedMemorySize, SMEM);

    setup_mats<<<1, 64>>>(vp);

    int B = in_sizes[0] / DIM;
    qsim_kernel<<<B, NT, SMEM>>>(sr, si, hw, hb, out);
}